// round 1
// baseline (speedup 1.0000x reference)
#include <cuda_runtime.h>

// Problem constants (fixed shapes from setup_inputs)
#define BB 32
#define HH 480
#define WW 640
#define HWsz (HH*WW)          // 307200
#define CIM 3
#define OHh 34
#define OWw 45
#define NR 1530               // OHh*OWw
#define KTOP 153              // max(int(0.1*1530),10)
#define RESH 14
#define PHLF 12               // patch half (ks=25)
#define PSZ 625               // 25*25
#define EPSf 1e-5f
#define MIN_SAMP 4
#define NBG 32                // blocks per batch for global passes
#define CHUNK (HWsz/NBG)      // 9600

// ----------------------------- scratch (static device memory only) ---------
__device__ int      d_mode;                    // 0=u8, 1=int32, 2=float32 masks
__device__ float    d_resized[BB*NR];
__device__ int      d_coords[BB*KTOP*2];
__device__ float    d_ep[BB*KTOP];
__device__ int      d_validp[BB*KTOP];
__device__ float    d_epatch[BB];
__device__ unsigned d_hist1[BB*2*2048];
__device__ unsigned d_hist2[BB*2*2048];
__device__ unsigned d_hist3[BB*2*1024];
__device__ unsigned d_ncnt[BB];
__device__ unsigned d_sel1[BB*2];
__device__ unsigned d_cb1[BB*2];
__device__ unsigned d_sel12[BB*2];
__device__ unsigned d_cb2[BB*2];
__device__ float    d_med[BB*2];
__device__ float    d_scale[BB*2];
__device__ float    d_spart[BB*2*NBG];
__device__ float    d_gpart[BB*NBG];

// ----------------------------- helpers -------------------------------------
__device__ __forceinline__ bool mget(const void* m, int i, int mode){
    if(mode==1) return ((const int*)m)[i]!=0;
    if(mode==2) return ((const float*)m)[i]!=0.0f;
    return ((const unsigned char*)m)[i]!=0;
}
__device__ __forceinline__ unsigned keyf(float v){
    unsigned b=__float_as_uint(v);
    return b ^ ((b & 0x80000000u) ? 0xFFFFFFFFu : 0x80000000u);
}
__device__ __forceinline__ float unkey(unsigned k){
    unsigned b = (k & 0x80000000u) ? (k ^ 0x80000000u) : ~k;
    return __uint_as_float(b);
}
// 256-thread block sum (red must hold 256 floats)
__device__ __forceinline__ float bsum256(float v, float* red, int t){
    red[t]=v; __syncthreads();
    #pragma unroll
    for(int s=128;s>0;s>>=1){ if(t<s) red[t]+=red[t+s]; __syncthreads(); }
    float r=red[0]; __syncthreads();
    return r;
}

// ----------------------------- mask dtype detection -------------------------
__global__ void k_detect(const unsigned* m){
    if(threadIdx.x==0 && blockIdx.x==0){
        bool allb=true, allf=true;
        for(int i=0;i<64;i++){
            unsigned v=m[i];
            allb = allb && (v<=1u);
            allf = allf && (v==0u || v==0x3F800000u);
        }
        d_mode = allb ? 1 : (allf ? 2 : 0);
    }
}

// ----------------------------- zero scratch ---------------------------------
__global__ void k_zero(){
    int i=blockIdx.x*blockDim.x+threadIdx.x;
    if(i<BB*2*2048){ d_hist1[i]=0u; d_hist2[i]=0u; }
    if(i<BB*2*1024) d_hist3[i]=0u;
    if(i<BB) d_ncnt[i]=0u;
}

// ----------------------------- edge + bilinear resize ------------------------
__device__ float edge_at(const float* img, const void* vm, int b, int y, int x, int mode){
    if(y<3 || y>HH-4 || x<3 || x>WW-4) return 0.f;          // 3-px border mask
    // eroded validity mask: need full 3x3 of vmask set
    bool ok=true;
    #pragma unroll
    for(int dy=-1;dy<=1;dy++)
        #pragma unroll
        for(int dx=-1;dx<=1;dx++)
            ok = ok && mget(vm, b*HWsz+(y+dy)*WW+(x+dx), mode);
    if(!ok) return 0.f;
    float gx2=0.f, gy2=0.f;
    #pragma unroll
    for(int c=0;c<CIM;c++){
        const float* p = img + (size_t)(b*CIM+c)*HWsz;
        float v00=p[(y-1)*WW+x-1], v01=p[(y-1)*WW+x], v02=p[(y-1)*WW+x+1];
        float v10=p[(y  )*WW+x-1],                    v12=p[(y  )*WW+x+1];
        float v20=p[(y+1)*WW+x-1], v21=p[(y+1)*WW+x], v22=p[(y+1)*WW+x+1];
        float sx=((v02+2.f*v12+v22)-(v00+2.f*v10+v20))*0.125f;
        float sy=((v20+2.f*v21+v22)-(v00+2.f*v01+v02))*0.125f;
        gx2+=sx*sx; gy2+=sy*sy;
    }
    return sqrtf((gx2+gy2)*(1.f/3.f));   // sqrt(mean gx^2 + mean gy^2)
}

__global__ void k_edge(const float* img, const void* vm){
    int id=blockIdx.x*blockDim.x+threadIdx.x;
    if(id>=BB*NR) return;
    int mode=d_mode;
    int b=id/NR, o=id%NR, oy=o/OWw, ox=o%OWw;
    const float ry=(float)(480.0/34.0), rx=(float)(640.0/45.0);
    float cy=fminf(fmaxf((oy+0.5f)*ry-0.5f,0.f),(float)(HH-1));
    float cx=fminf(fmaxf((ox+0.5f)*rx-0.5f,0.f),(float)(WW-1));
    int y0=(int)floorf(cy), x0=(int)floorf(cx);
    int y1=min(y0+1,HH-1),  x1=min(x0+1,WW-1);
    float wy=cy-(float)y0,  wx=cx-(float)x0;
    float e00=edge_at(img,vm,b,y0,x0,mode);
    float e01=edge_at(img,vm,b,y0,x1,mode);
    float e10=edge_at(img,vm,b,y1,x0,mode);
    float e11=edge_at(img,vm,b,y1,x1,mode);
    d_resized[id]= e00*(1.f-wy)*(1.f-wx)+e01*(1.f-wy)*wx
                 + e10*wy*(1.f-wx)      +e11*wy*wx;
}

// ----------------------------- top-k (per batch, bitonic) --------------------
__global__ __launch_bounds__(512) void k_topk(){
    __shared__ unsigned long long sk[2048];
    int b=blockIdx.x, t=threadIdx.x;
    for(int i=t;i<2048;i+=512){
        if(i<NR){
            unsigned vb=__float_as_uint(d_resized[b*NR+i]);  // values >= 0
            sk[i]=((unsigned long long)vb<<32)|(unsigned long long)(0xFFFFFFFFu-(unsigned)i);
        } else sk[i]=0ull;
    }
    __syncthreads();
    for(int k2=2;k2<=2048;k2<<=1){
        for(int j=k2>>1;j>0;j>>=1){
            for(int i=t;i<2048;i+=512){
                int l=i^j;
                if(l>i){
                    bool up=((i&k2)==0);
                    unsigned long long a=sk[i], bv=sk[l];
                    if((a>bv)==up){ sk[i]=bv; sk[l]=a; }
                }
            }
            __syncthreads();
        }
    }
    if(t<KTOP){
        unsigned long long key=sk[2047-t];
        unsigned idx=0xFFFFFFFFu-(unsigned)(key&0xFFFFFFFFull);
        d_coords[(b*KTOP+t)*2+0]=(int)(idx/OWw)*RESH;
        d_coords[(b*KTOP+t)*2+1]=(int)(idx%OWw)*RESH;
    }
}

// ----------------------------- per-patch SSI loss ---------------------------
__device__ float patch_median(const float* arr, const unsigned char* sm, float* sv, int t, int n){
    const float INF=__int_as_float(0x7f800000);
    for(int i=t;i<1024;i+=256) sv[i]=(i<PSZ && sm[i])?arr[i]:INF;
    __syncthreads();
    for(int k2=2;k2<=1024;k2<<=1){
        for(int j=k2>>1;j>0;j>>=1){
            for(int i=t;i<1024;i+=256){
                int l=i^j;
                if(l>i){
                    bool up=((i&k2)==0);
                    float a=sv[i],bv=sv[l];
                    if((a>bv)==up){ sv[i]=bv; sv[l]=a; }
                }
            }
            __syncthreads();
        }
    }
    float med=(n>0)? sv[(n-1)>>1] : 0.f;
    __syncthreads();
    return med;
}

__global__ __launch_bounds__(256) void k_patch(const float* in, const float* tg, const void* mk){
    __shared__ float sv[1024];
    __shared__ float sa[PSZ];
    __shared__ float sb[PSZ];
    __shared__ unsigned char sm[PSZ];
    __shared__ float red[256];
    int blk=blockIdx.x;
    int b=blk/KTOP, p=blk%KTOP;
    int t=threadIdx.x;
    int mode=d_mode;
    int cy=d_coords[(b*KTOP+p)*2+0], cx=d_coords[(b*KTOP+p)*2+1];
    float nloc=0.f;
    for(int i=t;i<PSZ;i+=256){
        int y=cy+i/25-PHLF, x=cx+i%25-PHLF;
        bool inb=(y>=0)&&(y<HH)&&(x>=0)&&(x<WW);
        bool m=inb && mget(mk, b*HWsz+y*WW+x, mode);
        sa[i]= inb ? in[(size_t)b*HWsz+y*WW+x] : 0.f;
        sb[i]= inb ? tg[(size_t)b*HWsz+y*WW+x] : 0.f;
        sm[i]=(unsigned char)m;
        nloc+= m?1.f:0.f;
    }
    __syncthreads();
    int n=(int)(bsum256(nloc,red,t)+0.5f);

    float medA=patch_median(sa,sm,sv,t,n);
    float medB=patch_median(sb,sm,sv,t,n);

    float s0=0.f,s1=0.f;
    for(int i=t;i<PSZ;i+=256) if(sm[i]){ s0+=fabsf(sa[i]-medA); s1+=fabsf(sb[i]-medB); }
    float nf=fmaxf((float)n,1.f);
    float sumA=bsum256(s0,red,t);
    float sumB=bsum256(s1,red,t);
    float scA=fmaxf(sumA/nf,EPSf), scB=fmaxf(sumB/nf,EPSf);

    float es=0.f;
    for(int i=t;i<PSZ;i+=256) if(sm[i]){
        float a=(sa[i]-medA)/scA, c=(sb[i]-medB)/scB;
        es+=fmaxf(fabsf(a-c),EPSf);
    }
    float errsum=bsum256(es,red,t);
    if(t==0){
        d_ep[blk]=sqrtf(fmaxf(errsum/nf,EPSf));
        d_validp[blk]=(n>=MIN_SAMP);
    }
}

__global__ __launch_bounds__(256) void k_preduce(){
    __shared__ float r0[256];
    __shared__ float r1[256];
    int b=blockIdx.x, t=threadIdx.x;
    float s=0.f,c=0.f;
    for(int i=t;i<KTOP;i+=256) if(d_validp[b*KTOP+i]){ s+=d_ep[b*KTOP+i]; c+=1.f; }
    r0[t]=s; r1[t]=c; __syncthreads();
    #pragma unroll
    for(int st=128;st>0;st>>=1){ if(t<st){r0[t]+=r0[t+st]; r1[t]+=r1[t+st];} __syncthreads(); }
    if(t==0) d_epatch[b]=r0[0]/fmaxf(r1[0],1.f);
}

// ----------------------------- global median: histogram radix select --------
__global__ __launch_bounds__(256) void k_hist1(const float* in, const float* tg, const void* mk){
    __shared__ unsigned h[4096];
    __shared__ unsigned rn[256];
    int b=blockIdx.y, t=threadIdx.x;
    for(int i=t;i<4096;i+=256) h[i]=0u;
    __syncthreads();
    int mode=d_mode;
    int base=b*HWsz+blockIdx.x*CHUNK;
    unsigned nloc=0;
    for(int i=t;i<CHUNK;i+=256){
        int gi=base+i;
        if(mget(mk,gi,mode)){
            nloc++;
            atomicAdd(&h[        keyf(in[gi])>>21 ],1u);
            atomicAdd(&h[2048u+(keyf(tg[gi])>>21)],1u);
        }
    }
    __syncthreads();
    for(int i=t;i<4096;i+=256){ unsigned v=h[i]; if(v) atomicAdd(&d_hist1[b*4096+i],v); }
    rn[t]=nloc; __syncthreads();
    #pragma unroll
    for(int st=128;st>0;st>>=1){ if(t<st) rn[t]+=rn[t+st]; __syncthreads(); }
    if(t==0) atomicAdd(&d_ncnt[b],rn[0]);
}

__global__ __launch_bounds__(256) void k_hist2(const float* in, const float* tg, const void* mk){
    __shared__ unsigned h[4096];
    int b=blockIdx.y, t=threadIdx.x;
    for(int i=t;i<4096;i+=256) h[i]=0u;
    __syncthreads();
    int mode=d_mode;
    unsigned s0=d_sel1[b*2+0], s1=d_sel1[b*2+1];
    int base=b*HWsz+blockIdx.x*CHUNK;
    for(int i=t;i<CHUNK;i+=256){
        int gi=base+i;
        if(mget(mk,gi,mode)){
            unsigned ki=keyf(in[gi]);
            if((ki>>21)==s0) atomicAdd(&h[(ki>>10)&0x7FFu],1u);
            unsigned kt=keyf(tg[gi]);
            if((kt>>21)==s1) atomicAdd(&h[2048u+((kt>>10)&0x7FFu)],1u);
        }
    }
    __syncthreads();
    for(int i=t;i<4096;i+=256){ unsigned v=h[i]; if(v) atomicAdd(&d_hist2[b*4096+i],v); }
}

__global__ __launch_bounds__(256) void k_hist3(const float* in, const float* tg, const void* mk){
    __shared__ unsigned h[2048];
    int b=blockIdx.y, t=threadIdx.x;
    for(int i=t;i<2048;i+=256) h[i]=0u;
    __syncthreads();
    int mode=d_mode;
    unsigned s0=d_sel12[b*2+0], s1=d_sel12[b*2+1];
    int base=b*HWsz+blockIdx.x*CHUNK;
    for(int i=t;i<CHUNK;i+=256){
        int gi=base+i;
        if(mget(mk,gi,mode)){
            unsigned ki=keyf(in[gi]);
            if((ki>>10)==s0) atomicAdd(&h[ki&0x3FFu],1u);
            unsigned kt=keyf(tg[gi]);
            if((kt>>10)==s1) atomicAdd(&h[1024u+(kt&0x3FFu)],1u);
        }
    }
    __syncthreads();
    for(int i=t;i<2048;i+=256){ unsigned v=h[i]; if(v) atomicAdd(&d_hist3[b*2048+i],v); }
}

__global__ __launch_bounds__(256) void k_select(int level){
    int bt=blockIdx.x; int b=bt>>1, tt=bt&1, t=threadIdx.x;
    unsigned n=d_ncnt[b];
    const unsigned* hist;
    int nbins;
    if(level==1){ hist=&d_hist1[b*4096+tt*2048]; nbins=2048; }
    else if(level==2){ hist=&d_hist2[b*4096+tt*2048]; nbins=2048; }
    else { hist=&d_hist3[b*2048+tt*1024]; nbins=1024; }
    int per=nbins/256;
    __shared__ unsigned part[256];
    unsigned loc=0;
    for(int i=0;i<per;i++) loc+=hist[t*per+i];
    part[t]=loc; __syncthreads();
    if(t!=0) return;
    bool dead=(n==0);
    unsigned kmed=(n>0)?((n-1u)>>1):0u;
    unsigned kk=kmed;
    if(level==2){ if(d_sel1 [bt]==0xFFFFFFFFu) dead=true; else kk=kmed-d_cb1[bt]; }
    if(level==3){ if(d_sel12[bt]==0xFFFFFFFFu) dead=true; else kk=kmed-d_cb2[bt]; }
    if(dead){
        if(level==1) d_sel1 [bt]=0xFFFFFFFFu;
        else if(level==2) d_sel12[bt]=0xFFFFFFFFu;
        else d_med[bt]=0.f;
        return;
    }
    unsigned cum=0; int c=0;
    while(c<256 && cum+part[c]<=kk){ cum+=part[c]; c++; }
    int bin=c*per;
    while(cum+hist[bin]<=kk){ cum+=hist[bin]; bin++; }
    if(level==1){ d_sel1[bt]=(unsigned)bin; d_cb1[bt]=cum; }
    else if(level==2){ d_sel12[bt]=(d_sel1[bt]<<11)|(unsigned)bin; d_cb2[bt]=d_cb1[bt]+cum; }
    else { unsigned key=(d_sel12[bt]<<10)|(unsigned)bin; d_med[bt]=unkey(key); }
}

// ----------------------------- global scale + error passes ------------------
__global__ __launch_bounds__(256) void k_scale(const float* in, const float* tg, const void* mk){
    __shared__ float red[256];
    int b=blockIdx.y, t=threadIdx.x, bx=blockIdx.x;
    int mode=d_mode;
    float m0=d_med[b*2+0], m1=d_med[b*2+1];
    int base=b*HWsz+bx*CHUNK;
    float s0=0.f,s1=0.f;
    for(int i=t;i<CHUNK;i+=256){
        int gi=base+i;
        if(mget(mk,gi,mode)){ s0+=fabsf(in[gi]-m0); s1+=fabsf(tg[gi]-m1); }
    }
    float r0=bsum256(s0,red,t);
    float r1=bsum256(s1,red,t);
    if(t==0){ d_spart[(b*2+0)*NBG+bx]=r0; d_spart[(b*2+1)*NBG+bx]=r1; }
}

__global__ void k_sred(){
    int b=blockIdx.x, t=threadIdx.x;
    if(t<2){
        float s=0.f;
        for(int i=0;i<NBG;i++) s+=d_spart[(b*2+t)*NBG+i];
        d_scale[b*2+t]= s / fmaxf((float)d_ncnt[b],1.f);
    }
}

__global__ __launch_bounds__(256) void k_gerr(const float* in, const float* tg, const void* mk){
    __shared__ float red[256];
    int b=blockIdx.y, t=threadIdx.x, bx=blockIdx.x;
    int mode=d_mode;
    float m0=d_med[b*2+0], m1=d_med[b*2+1];
    float s0=fmaxf(d_scale[b*2+0],EPSf), s1=fmaxf(d_scale[b*2+1],EPSf);
    int base=b*HWsz+bx*CHUNK;
    float acc=0.f;
    for(int i=t;i<CHUNK;i+=256){
        int gi=base+i;
        if(mget(mk,gi,mode)){
            float a=(in[gi]-m0)/s0, c=(tg[gi]-m1)/s1;
            acc+=fmaxf(fabsf(a-c),EPSf);
        }
    }
    float r=bsum256(acc,red,t);
    if(t==0) d_gpart[b*NBG+bx]=r;
}

__global__ void k_final(float* out){
    int b=blockIdx.x, t=threadIdx.x;
    if(t==0){
        float s=0.f;
        for(int i=0;i<NBG;i++) s+=d_gpart[b*NBG+i];
        float n=fmaxf((float)d_ncnt[b],1.f);
        float eg=sqrtf(fmaxf(s/n,EPSf));
        out[b]=0.5f*(d_epatch[b]+eg);
    }
}

// ----------------------------- launch ---------------------------------------
extern "C" void kernel_launch(void* const* d_in, const int* in_sizes, int n_in,
                              void* d_out, int out_size){
    const float* in =(const float*)d_in[0];
    const float* tg =(const float*)d_in[1];
    const void*  mk = d_in[2];
    const float* img=(const float*)d_in[3];
    const void*  vm = d_in[4];
    float* out=(float*)d_out;
    (void)in_sizes; (void)n_in; (void)out_size;

    k_detect<<<1,32>>>((const unsigned*)mk);
    k_zero<<<512,256>>>();
    k_edge<<<(BB*NR+255)/256,256>>>(img,vm);
    k_topk<<<BB,512>>>();
    k_patch<<<BB*KTOP,256>>>(in,tg,mk);
    k_preduce<<<BB,256>>>();
    dim3 g(NBG,BB);
    k_hist1<<<g,256>>>(in,tg,mk);
    k_select<<<BB*2,256>>>(1);
    k_hist2<<<g,256>>>(in,tg,mk);
    k_select<<<BB*2,256>>>(2);
    k_hist3<<<g,256>>>(in,tg,mk);
    k_select<<<BB*2,256>>>(3);
    k_scale<<<g,256>>>(in,tg,mk);
    k_sred<<<BB,32>>>();
    k_gerr<<<g,256>>>(in,tg,mk);
    k_final<<<BB,32>>>(out);
}

// round 2
// speedup vs baseline: 3.6616x; 3.6616x over previous
#include <cuda_runtime.h>

// Problem constants (fixed shapes from setup_inputs)
#define BB 32
#define HH 480
#define WW 640
#define HWsz (HH*WW)          // 307200
#define CIM 3
#define OHh 34
#define OWw 45
#define NR 1530               // OHh*OWw
#define KTOP 153              // max(int(0.1*1530),10)
#define RESH 14
#define PHLF 12               // patch half (ks=25)
#define PSZ 625               // 25*25
#define EPSf 1e-5f
#define MIN_SAMP 4
#define NBG 30                // blocks per batch for global passes
#define CHUNK (HWsz/NBG)      // 10240 (divisible by 1024)

// ----------------------------- scratch (static device memory only) ---------
__device__ int      d_mode;                    // 0=u8, 1=int32, 2=float32 masks
__device__ unsigned d_mbits[BB*HWsz/32];       // packed mask bits (1.2MB)
__device__ float    d_resized[BB*NR];
__device__ int      d_coords[BB*KTOP*2];
__device__ float    d_ep[BB*KTOP];
__device__ int      d_validp[BB*KTOP];
__device__ float    d_epatch[BB];
__device__ unsigned d_hist1[BB*2*2048];
__device__ unsigned d_hist2[BB*2*2048];
__device__ unsigned d_hist3[BB*2*1024];
__device__ unsigned d_ncnt[BB];
__device__ unsigned d_sel1[BB*2];
__device__ unsigned d_cb1[BB*2];
__device__ unsigned d_sel12[BB*2];
__device__ unsigned d_cb2[BB*2];
__device__ float    d_med[BB*2];
__device__ float    d_scale[BB*2];
__device__ float    d_vsum[BB*2];              // masked sum of values per (b,arr)
__device__ float    d_slo[BB*2];               // masked sum of values with key>>10 < sel12
__device__ float    d_gsum[BB];                // global error partials

// ----------------------------- helpers -------------------------------------
__device__ __forceinline__ bool mget(const void* m, int i, int mode){
    if(mode==1) return ((const int*)m)[i]!=0;
    if(mode==2) return ((const float*)m)[i]!=0.0f;
    return ((const unsigned char*)m)[i]!=0;
}
__device__ __forceinline__ unsigned keyf(float v){
    unsigned b=__float_as_uint(v);
    return b ^ ((b & 0x80000000u) ? 0xFFFFFFFFu : 0x80000000u);
}
__device__ __forceinline__ float unkey(unsigned k){
    unsigned b = (k & 0x80000000u) ? (k ^ 0x80000000u) : ~k;
    return __uint_as_float(b);
}
// 256-thread block sum
__device__ __forceinline__ float bsum256(float v, float* red, int t){
    red[t]=v; __syncthreads();
    #pragma unroll
    for(int s=128;s>0;s>>=1){ if(t<s) red[t]+=red[t+s]; __syncthreads(); }
    float r=red[0]; __syncthreads();
    return r;
}

// Generic 4-level (8 bits each) radix select of ascending rank kk among the
// valid keys distributed across a 256-thread block (NOWN keys per thread, in
// registers). Returns the selected full 32-bit key.
template<int NOWN>
__device__ __forceinline__ unsigned radix_sel(const unsigned (&key)[NOWN],
                                              const bool (&vl)[NOWN],
                                              unsigned kk,
                                              unsigned* hist, unsigned* wsum,
                                              unsigned* shb){
    int t=threadIdx.x, lane=t&31, wid=t>>5;
    unsigned prefix=0u;
    #pragma unroll
    for(int lvl=0;lvl<4;lvl++){
        const int sh=24-8*lvl;
        hist[t]=0u; __syncthreads();
        #pragma unroll
        for(int r=0;r<NOWN;r++) if(vl[r]){
            unsigned k=key[r];
            bool ok = (lvl==0) || ((k>>(sh+8))==prefix);
            if(ok) atomicAdd(&hist[(k>>sh)&255u],1u);
        }
        __syncthreads();
        unsigned c=hist[t], x=c;
        #pragma unroll
        for(int o=1;o<32;o<<=1){ unsigned v=__shfl_up_sync(0xffffffffu,x,o); if(lane>=o)x+=v; }
        if(lane==31) wsum[wid]=x;
        __syncthreads();
        if(t<8){
            unsigned w=wsum[t];
            #pragma unroll
            for(int o=1;o<8;o<<=1){ unsigned v=__shfl_up_sync(0xffu,w,o); if(t>=o)w+=v; }
            wsum[t]=w;
        }
        __syncthreads();
        unsigned incl = x + (wid? wsum[wid-1]:0u);
        unsigned excl = incl - c;
        if(excl<=kk && kk<incl){ shb[0]=(unsigned)t; shb[1]=excl; }
        __syncthreads();
        prefix = (prefix<<8) | shb[0];
        kk -= shb[1];
        __syncthreads();
    }
    return prefix;
}

// warp-aggregated histogram increment (all 32 lanes must call; sentinel skips)
__device__ __forceinline__ void aggInc(unsigned* h, unsigned bn){
    unsigned mm=__match_any_sync(0xffffffffu,bn);
    if(bn!=0xFFFFFFFFu){
        int leader=__ffs(mm)-1;
        if((int)(threadIdx.x&31)==leader) atomicAdd(&h[bn],(unsigned)__popc(mm));
    }
}

// ----------------------------- mask dtype detection -------------------------
__global__ void k_detect(const unsigned* m){
    if(threadIdx.x==0 && blockIdx.x==0){
        bool allb=true, allf=true;
        for(int i=0;i<64;i++){
            unsigned v=m[i];
            allb = allb && (v<=1u);
            allf = allf && (v==0u || v==0x3F800000u);
        }
        d_mode = allb ? 1 : (allf ? 2 : 0);
    }
}

// ----------------------------- zero scratch ---------------------------------
__global__ void k_zero(){
    int i=blockIdx.x*blockDim.x+threadIdx.x;
    if(i<BB*2*2048){ d_hist1[i]=0u; d_hist2[i]=0u; }
    if(i<BB*2*1024) d_hist3[i]=0u;
    if(i<BB){ d_ncnt[i]=0u; d_gsum[i]=0.f; }
    if(i<BB*2){ d_vsum[i]=0.f; d_slo[i]=0.f; }
}

// ----------------------------- pack mask into bits ---------------------------
__global__ void k_pack(const void* mk){
    int gi=blockIdx.x*blockDim.x+threadIdx.x;   // over BB*HWsz (multiple of 256)
    int mode=d_mode;
    bool m=mget(mk,gi,mode);
    unsigned bal=__ballot_sync(0xffffffffu,m);
    if((threadIdx.x&31)==0) d_mbits[gi>>5]=bal;
}

// ----------------------------- edge + bilinear resize ------------------------
__device__ float edge_at(const float* img, const void* vm, int b, int y, int x, int mode){
    if(y<3 || y>HH-4 || x<3 || x>WW-4) return 0.f;
    bool ok=true;
    #pragma unroll
    for(int dy=-1;dy<=1;dy++)
        #pragma unroll
        for(int dx=-1;dx<=1;dx++)
            ok = ok && mget(vm, b*HWsz+(y+dy)*WW+(x+dx), mode);
    if(!ok) return 0.f;
    float gx2=0.f, gy2=0.f;
    #pragma unroll
    for(int c=0;c<CIM;c++){
        const float* p = img + (size_t)(b*CIM+c)*HWsz;
        float v00=p[(y-1)*WW+x-1], v01=p[(y-1)*WW+x], v02=p[(y-1)*WW+x+1];
        float v10=p[(y  )*WW+x-1],                    v12=p[(y  )*WW+x+1];
        float v20=p[(y+1)*WW+x-1], v21=p[(y+1)*WW+x], v22=p[(y+1)*WW+x+1];
        float sx=((v02+2.f*v12+v22)-(v00+2.f*v10+v20))*0.125f;
        float sy=((v20+2.f*v21+v22)-(v00+2.f*v01+v02))*0.125f;
        gx2+=sx*sx; gy2+=sy*sy;
    }
    return sqrtf((gx2+gy2)*(1.f/3.f));
}

__global__ void k_edge(const float* img, const void* vm){
    int id=blockIdx.x*blockDim.x+threadIdx.x;
    if(id>=BB*NR) return;
    int mode=d_mode;
    int b=id/NR, o=id%NR, oy=o/OWw, ox=o%OWw;
    const float ry=(float)(480.0/34.0), rx=(float)(640.0/45.0);
    float cy=fminf(fmaxf((oy+0.5f)*ry-0.5f,0.f),(float)(HH-1));
    float cx=fminf(fmaxf((ox+0.5f)*rx-0.5f,0.f),(float)(WW-1));
    int y0=(int)floorf(cy), x0=(int)floorf(cx);
    int y1=min(y0+1,HH-1),  x1=min(x0+1,WW-1);
    float wy=cy-(float)y0,  wx=cx-(float)x0;
    float e00=edge_at(img,vm,b,y0,x0,mode);
    float e01=edge_at(img,vm,b,y0,x1,mode);
    float e10=edge_at(img,vm,b,y1,x0,mode);
    float e11=edge_at(img,vm,b,y1,x1,mode);
    d_resized[id]= e00*(1.f-wy)*(1.f-wx)+e01*(1.f-wy)*wx
                 + e10*wy*(1.f-wx)      +e11*wy*wx;
}

// ----------------------------- top-k via radix threshold ---------------------
__global__ __launch_bounds__(256) void k_topk(){
    __shared__ unsigned hist[256];
    __shared__ unsigned wsum[8];
    __shared__ unsigned shb[2];
    __shared__ int ties[NR];
    __shared__ int cnt_gt, cnt_tie;
    int b=blockIdx.x, t=threadIdx.x;
    unsigned key[6]; bool vl[6];
    #pragma unroll
    for(int r=0;r<6;r++){
        int i=t+256*r;
        vl[r]=(i<NR);
        key[r]= vl[r] ? keyf(d_resized[b*NR+i]) : 0u;
    }
    if(t==0){ cnt_gt=0; cnt_tie=0; }
    __syncthreads();
    unsigned T=radix_sel<6>(key,vl,(unsigned)(NR-KTOP),hist,wsum,shb);
    #pragma unroll
    for(int r=0;r<6;r++) if(vl[r]){
        int i=t+256*r;
        if(key[r]>T){
            int s=atomicAdd(&cnt_gt,1);
            d_coords[(b*KTOP+s)*2+0]=(i/OWw)*RESH;
            d_coords[(b*KTOP+s)*2+1]=(i%OWw)*RESH;
        } else if(key[r]==T){
            int s=atomicAdd(&cnt_tie,1);
            ties[s]=i;
        }
    }
    __syncthreads();
    int r_need=KTOP-cnt_gt;
    int nt=cnt_tie;
    for(int j=t;j<nt;j+=256){
        int idx=ties[j]; int rk=0;
        for(int q=0;q<nt;q++) rk += (ties[q]<idx);
        if(rk<r_need){
            int s=cnt_gt+rk;
            d_coords[(b*KTOP+s)*2+0]=(idx/OWw)*RESH;
            d_coords[(b*KTOP+s)*2+1]=(idx%OWw)*RESH;
        }
    }
}

// ----------------------------- per-patch SSI loss (radix median) ------------
__global__ __launch_bounds__(256) void k_patch(const float* __restrict__ in,
                                               const float* __restrict__ tg){
    __shared__ unsigned hist[256];
    __shared__ unsigned wsum[8];
    __shared__ unsigned shb[2];
    __shared__ float red[256];
    int blk=blockIdx.x;
    int b=blk/KTOP, p=blk%KTOP, t=threadIdx.x;
    int cy=d_coords[(b*KTOP+p)*2+0], cx=d_coords[(b*KTOP+p)*2+1];
    unsigned ka[3],kb[3]; float va[3],vb[3]; bool vl[3];
    int nown = 2 + (t<113);        // 625 = 2*256 + 113
    float nloc=0.f;
    #pragma unroll
    for(int r=0;r<3;r++){
        vl[r]=false; ka[r]=0u; kb[r]=0u; va[r]=0.f; vb[r]=0.f;
        if(r<nown){
            int i=t+256*r;
            int y=cy+i/25-PHLF, x=cx+i%25-PHLF;
            bool inb=(y>=0)&&(y<HH)&&(x>=0)&&(x<WW);
            if(inb){
                int gi=b*HWsz+y*WW+x;
                bool m=(d_mbits[gi>>5]>>(gi&31))&1u;
                if(m){
                    vl[r]=true;
                    va[r]=in[gi]; vb[r]=tg[gi];
                    ka[r]=keyf(va[r]); kb[r]=keyf(vb[r]);
                    nloc+=1.f;
                }
            }
        }
    }
    int n=(int)(bsum256(nloc,red,t)+0.5f);
    float medA=0.f, medB=0.f;
    if(n>0){
        unsigned kk=(unsigned)((n-1)>>1);
        medA=unkey(radix_sel<3>(ka,vl,kk,hist,wsum,shb));
        medB=unkey(radix_sel<3>(kb,vl,kk,hist,wsum,shb));
    }
    float s0=0.f,s1=0.f;
    #pragma unroll
    for(int r=0;r<3;r++) if(vl[r]){ s0+=fabsf(va[r]-medA); s1+=fabsf(vb[r]-medB); }
    float nf=fmaxf((float)n,1.f);
    float sumA=bsum256(s0,red,t);
    float sumB=bsum256(s1,red,t);
    float scA=fmaxf(sumA/nf,EPSf), scB=fmaxf(sumB/nf,EPSf);
    float rA=1.f/scA, rB=1.f/scB;
    float es=0.f;
    #pragma unroll
    for(int r=0;r<3;r++) if(vl[r]){
        float a=(va[r]-medA)*rA, c=(vb[r]-medB)*rB;
        es+=fmaxf(fabsf(a-c),EPSf);
    }
    float errsum=bsum256(es,red,t);
    if(t==0){
        d_ep[blk]=sqrtf(fmaxf(errsum/nf,EPSf));
        d_validp[blk]=(n>=MIN_SAMP);
    }
}

__global__ __launch_bounds__(256) void k_preduce(){
    __shared__ float r0[256];
    __shared__ float r1[256];
    int b=blockIdx.x, t=threadIdx.x;
    float s=0.f,c=0.f;
    for(int i=t;i<KTOP;i+=256) if(d_validp[b*KTOP+i]){ s+=d_ep[b*KTOP+i]; c+=1.f; }
    r0[t]=s; r1[t]=c; __syncthreads();
    #pragma unroll
    for(int st=128;st>0;st>>=1){ if(t<st){r0[t]+=r0[t+st]; r1[t]+=r1[t+st];} __syncthreads(); }
    if(t==0) d_epatch[b]=r0[0]/fmaxf(r1[0],1.f);
}

// ----------------------------- global median pass 1 --------------------------
__global__ __launch_bounds__(256) void k_hist1(const float* __restrict__ in,
                                               const float* __restrict__ tg){
    __shared__ unsigned h[4096];
    __shared__ float red[256];
    int b=blockIdx.y, t=threadIdx.x;
    for(int i=t;i<4096;i+=256) h[i]=0u;
    __syncthreads();
    int fbase=(b*HWsz+blockIdx.x*CHUNK)>>2;
    float sI=0.f,sT=0.f; float nloc=0.f;
    #pragma unroll 2
    for(int j=0;j<CHUNK/1024;j++){
        int f=fbase+j*256+t;
        unsigned mb=(d_mbits[f>>3]>>((f&7)*4))&0xFu;
        float4 vi=((const float4*)in)[f];
        float4 vt=((const float4*)tg)[f];
        float ei[4]={vi.x,vi.y,vi.z,vi.w};
        float et[4]={vt.x,vt.y,vt.z,vt.w};
        #pragma unroll
        for(int e=0;e<4;e++){
            bool a=(mb>>e)&1u;
            unsigned bi = a ? (keyf(ei[e])>>21) : 0xFFFFFFFFu;
            aggInc(h,bi);
            unsigned bt2 = a ? (2048u+(keyf(et[e])>>21)) : 0xFFFFFFFFu;
            aggInc(h,bt2);
            if(a){ nloc+=1.f; sI+=ei[e]; sT+=et[e]; }
        }
    }
    __syncthreads();
    for(int i=t;i<4096;i+=256){ unsigned v=h[i]; if(v) atomicAdd(&d_hist1[b*4096+i],v); }
    float rn=bsum256(nloc,red,t);
    float r0=bsum256(sI,red,t);
    float r1=bsum256(sT,red,t);
    if(t==0){
        atomicAdd(&d_ncnt[b],(unsigned)(rn+0.5f));
        atomicAdd(&d_vsum[b*2+0],r0);
        atomicAdd(&d_vsum[b*2+1],r1);
    }
}

__global__ __launch_bounds__(256) void k_hist2(const float* __restrict__ in,
                                               const float* __restrict__ tg){
    __shared__ unsigned h[4096];
    int b=blockIdx.y, t=threadIdx.x;
    for(int i=t;i<4096;i+=256) h[i]=0u;
    __syncthreads();
    unsigned s0=d_sel1[b*2+0], s1=d_sel1[b*2+1];
    int fbase=(b*HWsz+blockIdx.x*CHUNK)>>2;
    #pragma unroll 2
    for(int j=0;j<CHUNK/1024;j++){
        int f=fbase+j*256+t;
        unsigned mb=(d_mbits[f>>3]>>((f&7)*4))&0xFu;
        float4 vi=((const float4*)in)[f];
        float4 vt=((const float4*)tg)[f];
        float ei[4]={vi.x,vi.y,vi.z,vi.w};
        float et[4]={vt.x,vt.y,vt.z,vt.w};
        #pragma unroll
        for(int e=0;e<4;e++){
            if((mb>>e)&1u){
                unsigned ki=keyf(ei[e]);
                if((ki>>21)==s0) atomicAdd(&h[(ki>>10)&0x7FFu],1u);
                unsigned kt=keyf(et[e]);
                if((kt>>21)==s1) atomicAdd(&h[2048u+((kt>>10)&0x7FFu)],1u);
            }
        }
    }
    __syncthreads();
    for(int i=t;i<4096;i+=256){ unsigned v=h[i]; if(v) atomicAdd(&d_hist2[b*4096+i],v); }
}

__global__ __launch_bounds__(256) void k_hist3(const float* __restrict__ in,
                                               const float* __restrict__ tg){
    __shared__ unsigned h[2048];
    __shared__ float red[256];
    int b=blockIdx.y, t=threadIdx.x;
    for(int i=t;i<2048;i+=256) h[i]=0u;
    __syncthreads();
    unsigned s0=d_sel12[b*2+0], s1=d_sel12[b*2+1];
    int fbase=(b*HWsz+blockIdx.x*CHUNK)>>2;
    float lo0=0.f, lo1=0.f;
    #pragma unroll 2
    for(int j=0;j<CHUNK/1024;j++){
        int f=fbase+j*256+t;
        unsigned mb=(d_mbits[f>>3]>>((f&7)*4))&0xFu;
        float4 vi=((const float4*)in)[f];
        float4 vt=((const float4*)tg)[f];
        float ei[4]={vi.x,vi.y,vi.z,vi.w};
        float et[4]={vt.x,vt.y,vt.z,vt.w};
        #pragma unroll
        for(int e=0;e<4;e++){
            if((mb>>e)&1u){
                unsigned ki=keyf(ei[e]);
                unsigned pi=ki>>10;
                if(pi==s0) atomicAdd(&h[ki&0x3FFu],1u);
                else if(pi<s0) lo0+=ei[e];
                unsigned kt=keyf(et[e]);
                unsigned pt=kt>>10;
                if(pt==s1) atomicAdd(&h[1024u+(kt&0x3FFu)],1u);
                else if(pt<s1) lo1+=et[e];
            }
        }
    }
    __syncthreads();
    for(int i=t;i<2048;i+=256){ unsigned v=h[i]; if(v) atomicAdd(&d_hist3[b*2048+i],v); }
    float r0=bsum256(lo0,red,t);
    float r1=bsum256(lo1,red,t);
    if(t==0){
        atomicAdd(&d_slo[b*2+0],r0);
        atomicAdd(&d_slo[b*2+1],r1);
    }
}

// ----------------------------- selects ---------------------------------------
__global__ __launch_bounds__(256) void k_select(int level){
    int bt=blockIdx.x; int b=bt>>1, tt=bt&1, t=threadIdx.x;
    unsigned n=d_ncnt[b];
    const unsigned* hist = (level==1)? &d_hist1[b*4096+tt*2048] : &d_hist2[b*4096+tt*2048];
    const int per=8;  // 2048/256
    __shared__ unsigned part[256];
    unsigned loc=0;
    for(int i=0;i<per;i++) loc+=hist[t*per+i];
    part[t]=loc; __syncthreads();
    if(t!=0) return;
    bool dead=(n==0);
    unsigned kmed=(n>0)?((n-1u)>>1):0u;
    unsigned kk=kmed;
    if(level==2){ if(d_sel1[bt]==0xFFFFFFFFu) dead=true; else kk=kmed-d_cb1[bt]; }
    if(dead){
        if(level==1) d_sel1[bt]=0xFFFFFFFFu;
        else d_sel12[bt]=0xFFFFFFFFu;
        return;
    }
    unsigned cum=0; int c=0;
    while(c<256 && cum+part[c]<=kk){ cum+=part[c]; c++; }
    int bin=c*per;
    while(cum+hist[bin]<=kk){ cum+=hist[bin]; bin++; }
    if(level==1){ d_sel1[bt]=(unsigned)bin; d_cb1[bt]=cum; }
    else { d_sel12[bt]=(d_sel1[bt]<<11)|(unsigned)bin; d_cb2[bt]=d_cb1[bt]+cum; }
}

// level 3: exact median AND exact scale (mean|x-med|) from counts
__global__ __launch_bounds__(256) void k_select3(){
    int bt=blockIdx.x; int b=bt>>1, tt=bt&1, t=threadIdx.x;
    const unsigned* hist=&d_hist3[b*2048+tt*1024];
    __shared__ unsigned part[256];
    __shared__ unsigned sh_bin;
    __shared__ float rf[256];
    unsigned c4[4]; unsigned loc=0;
    #pragma unroll
    for(int i=0;i<4;i++){ c4[i]=hist[t*4+i]; loc+=c4[i]; }
    part[t]=loc; __syncthreads();
    unsigned n=d_ncnt[b];
    if(t==0){
        bool dead=(n==0)||(d_sel12[bt]==0xFFFFFFFFu);
        if(dead){ d_med[bt]=0.f; d_scale[bt]=0.f; sh_bin=0xFFFFFFFFu; }
        else{
            unsigned kk=((n-1u)>>1)-d_cb2[bt];
            unsigned cum=0; int c=0;
            while(c<256 && cum+part[c]<=kk){ cum+=part[c]; c++; }
            int bin=c*4;
            while(cum+hist[bin]<=kk){ cum+=hist[bin]; bin++; }
            sh_bin=(unsigned)bin;
        }
    }
    __syncthreads();
    unsigned bin=sh_bin;
    if(bin==0xFFFFFFFFu) return;
    unsigned pre=d_sel12[bt]<<10;
    float med=unkey(pre|bin);
    float slo=0.f, shi=0.f, clo=0.f, chi=0.f;
    #pragma unroll
    for(int i=0;i<4;i++){
        unsigned j=(unsigned)(t*4+i); unsigned c=c4[i];
        if(c){
            float v=unkey(pre|j);
            if(j<bin){ clo+=(float)c; slo+=(float)c*v; }
            else if(j>bin){ chi+=(float)c; shi+=(float)c*v; }
        }
    }
    slo=bsum256(slo,rf,t);
    shi=bsum256(shi,rf,t);
    clo=bsum256(clo,rf,t);
    chi=bsum256(chi,rf,t);
    if(t==0){
        float C_lo=(float)d_cb2[bt]+clo;
        float S_lo=d_slo[bt]+slo;
        float c_eq=(float)hist[bin];
        float C_hi=(float)n - C_lo - c_eq;
        float S_hi=d_vsum[bt] - S_lo - c_eq*med;
        float sumabs=(S_hi - C_hi*med) + (C_lo*med - S_lo);
        d_med[bt]=med;
        d_scale[bt]=sumabs/fmaxf((float)n,1.f);
    }
}

// ----------------------------- global error pass -----------------------------
__global__ __launch_bounds__(256) void k_gerr(const float* __restrict__ in,
                                              const float* __restrict__ tg){
    __shared__ float red[256];
    int b=blockIdx.y, t=threadIdx.x;
    float m0=d_med[b*2+0], m1=d_med[b*2+1];
    float r0=1.f/fmaxf(d_scale[b*2+0],EPSf), r1=1.f/fmaxf(d_scale[b*2+1],EPSf);
    int fbase=(b*HWsz+blockIdx.x*CHUNK)>>2;
    float acc=0.f;
    #pragma unroll 2
    for(int j=0;j<CHUNK/1024;j++){
        int f=fbase+j*256+t;
        unsigned mb=(d_mbits[f>>3]>>((f&7)*4))&0xFu;
        float4 vi=((const float4*)in)[f];
        float4 vt=((const float4*)tg)[f];
        float ei[4]={vi.x,vi.y,vi.z,vi.w};
        float et[4]={vt.x,vt.y,vt.z,vt.w};
        #pragma unroll
        for(int e=0;e<4;e++){
            if((mb>>e)&1u){
                float a=(ei[e]-m0)*r0, c=(et[e]-m1)*r1;
                acc+=fmaxf(fabsf(a-c),EPSf);
            }
        }
    }
    float r=bsum256(acc,red,t);
    if(t==0) atomicAdd(&d_gsum[b],r);
}

__global__ void k_final(float* out){
    int b=blockIdx.x;
    if(threadIdx.x==0){
        float n=fmaxf((float)d_ncnt[b],1.f);
        float eg=sqrtf(fmaxf(d_gsum[b]/n,EPSf));
        out[b]=0.5f*(d_epatch[b]+eg);
    }
}

// ----------------------------- launch ---------------------------------------
extern "C" void kernel_launch(void* const* d_in, const int* in_sizes, int n_in,
                              void* d_out, int out_size){
    const float* in =(const float*)d_in[0];
    const float* tg =(const float*)d_in[1];
    const void*  mk = d_in[2];
    const float* img=(const float*)d_in[3];
    const void*  vm = d_in[4];
    float* out=(float*)d_out;
    (void)in_sizes; (void)n_in; (void)out_size;

    k_detect<<<1,32>>>((const unsigned*)mk);
    k_zero<<<512,256>>>();
    k_pack<<<BB*HWsz/256,256>>>(mk);
    k_edge<<<(BB*NR+255)/256,256>>>(img,vm);
    k_topk<<<BB,256>>>();
    k_patch<<<BB*KTOP,256>>>(in,tg);
    k_preduce<<<BB,256>>>();
    dim3 g(NBG,BB);
    k_hist1<<<g,256>>>(in,tg);
    k_select<<<BB*2,256>>>(1);
    k_hist2<<<g,256>>>(in,tg);
    k_select<<<BB*2,256>>>(2);
    k_hist3<<<g,256>>>(in,tg);
    k_select3<<<BB*2,256>>>();
    k_gerr<<<g,256>>>(in,tg);
    k_final<<<BB,32>>>(out);
}